// round 14
// baseline (speedup 1.0000x reference)
#include <cuda_runtime.h>
#include <cstdint>

// Problem constants
#define BATCH      256
#define TREES      64
#define FEAT       16080        // 120*134
#define MASK_W     1000
#define K_TOP      200
#define ROW_F4     (FEAT / 4)   // 4020
#define LIVE_F4    (MASK_W / 4) // 250  (columns [0,1000) hold all nonzeros)
#define NROWS      (BATCH * TREES)   // 16384 rv rows
#define NROWS_ALL  (NROWS + TREES)   // + 64 attention rows = 16448

// ---------------------------------------------------------------------------
// Kernel A: block-per-tree exact top-200 via __syncthreads_count binary search.
//   Triggers programmatic launch completion at entry so the store kernel's
//   grid launches immediately and overlaps this one (64 blocks => all wave-1
//   resident => all triggers fire instantly).
// ---------------------------------------------------------------------------
__global__ __launch_bounds__(1024)
void topk_kernel(const float* __restrict__ mask, float* __restrict__ att_out)
{
    // Let the dependent rv_kernel grid begin launching now; its att-reading
    // blocks still wait for this grid's completion via
    // cudaGridDependencySynchronize().
    cudaTriggerProgrammaticLaunchCompletion();

    const int t   = blockIdx.x;
    const int tid = threadIdx.x;

    __shared__ unsigned int skey[1024];

    // Load + order-preserving float->uint transform
    float v = 0.0f;
    unsigned int key = 0u;
    if (tid < MASK_W) {
        v = mask[t * MASK_W + tid];
        const int s = __float_as_int(v);
        key = (s < 0) ? ~(unsigned int)s : ((unsigned int)s | 0x80000000u);
    }
    skey[tid] = key;   // consumed only on the rare tie path; the search-loop
                       // barriers below order this write before any read

    // Binary search: thr = max T with count(key >= T) >= K_TOP (200th largest).
    // Sentinel key 0 (tid >= 1000) is never counted: midpoints are >= 1 and
    // finite-float keys are > 0.
    unsigned int lo = 0u, hi = 0xFFFFFFFFu;
    while (lo < hi) {
        const unsigned int mid = lo + ((hi - lo) >> 1) + 1u;   // upper mid
        const int total = __syncthreads_count(key >= mid);
        if (total >= K_TOP) lo = mid; else hi = mid - 1u;
    }
    const unsigned int thr = lo;

    // Strictly-greater / equal counts (block-uniform results)
    const int cgt = __syncthreads_count(key > thr);
    const int ceq = __syncthreads_count(key == thr);
    const int need = K_TOP - cgt;            // equals to accept (1 <= need <= ceq)

    bool sel = (key > thr);
    if (key == thr) {
        if (need >= ceq) {
            sel = true;                      // all ties fit (common case)
        } else {                             // boundary tie: lowest indices win
            int r = 0;
            for (int j = 0; j < tid; ++j) r += (skey[j] == thr);
            sel = (r < need);
        }
    }

    if (tid < MASK_W) {
        att_out[(size_t)t * FEAT + tid] = sel ? (1.0f / (1.0f + expf(-v))) : 0.0f;
    }
}

// ---------------------------------------------------------------------------
// Kernel B: full-output store stream, 4 independent float4 stores per thread
//   (round-9 version + PDL dependency sync).
//   grid = (4, 16448), block = 256. base = bx*256+tid in [0,1024); thread
//   stores columns {base, base+1024, base+2048, base+3072} of its row.
//   Row-major grid: consecutive bids cover the 4 stripes of the same row,
//   so concurrent blocks write contiguous 16 KB spans (DRAM-page friendly).
//   Only bx==0 rv-row blocks read attention, so only they execute
//   cudaGridDependencySynchronize(); the other 75% of blocks stream zero
//   stores with no extra instructions — the store wave stays clean.
// ---------------------------------------------------------------------------
__global__ __launch_bounds__(256)
void rv_kernel(const float* __restrict__ x,
               const float* __restrict__ att,
               float*       __restrict__ out)
{
    const int tid  = threadIdx.x;
    const int base = blockIdx.x * 256 + tid;                 // 0 .. 1023
    const int row  = blockIdx.y;

    float4* dst = reinterpret_cast<float4*>(out + (size_t)row * FEAT);
    float4 z; z.x = 0.f; z.y = 0.f; z.z = 0.f; z.w = 0.f;

    if (row >= NROWS) {                    // attention row: zero tail only
        if (base >= LIVE_F4) dst[base] = z;
        dst[base + 1024] = z;
        dst[base + 2048] = z;
        if (base + 3072 < ROW_F4) dst[base + 3072] = z;
        return;
    }

    const int t = row & (TREES - 1);
    const int b = row >> 6;

    float4 r = z;
    if (base < LIVE_F4) {
        // Wait for topk_kernel's attention writes to be visible.
        cudaGridDependencySynchronize();
        const float4 xa = reinterpret_cast<const float4*>(x   + (size_t)b * FEAT)[base];
        const float4 aa = reinterpret_cast<const float4*>(att + (size_t)t * FEAT)[base];
        r.x = xa.x * aa.x;
        r.y = xa.y * aa.y;
        r.z = xa.z * aa.z;
        r.w = xa.w * aa.w;
    }
    dst[base]        = r;
    dst[base + 1024] = z;
    dst[base + 2048] = z;
    if (base + 3072 < ROW_F4) dst[base + 3072] = z;
}

// ---------------------------------------------------------------------------
// Launch: topk, then rv with programmatic stream serialization (PDL) so the
// rv grid launches and its independent blocks run while topk is in flight.
// ---------------------------------------------------------------------------
extern "C" void kernel_launch(void* const* d_in, const int* in_sizes, int n_in,
                              void* d_out, int out_size)
{
    const float* x    = (const float*)d_in[0];   // (256, 120, 134) fp32
    const float* mask = (const float*)d_in[1];   // (64, 1000) fp32

    float* out = (float*)d_out;
    float* att_out = out + (size_t)NROWS * FEAT; // (64, 16080) appended

    // A) block-per-tree exact top-200 -> attention[t, 0:1000)
    topk_kernel<<<TREES, 1024>>>(mask, att_out);

    // B) full-output store stream, launched with PDL overlap
    cudaLaunchConfig_t cfg = {};
    cfg.gridDim  = dim3(4, NROWS_ALL, 1);
    cfg.blockDim = dim3(256, 1, 1);
    cfg.dynamicSmemBytes = 0;
    cudaLaunchAttribute attr[1];
    attr[0].id = cudaLaunchAttributeProgrammaticStreamSerialization;
    attr[0].val.programmaticStreamSerializationAllowed = 1;
    cfg.attrs = attr;
    cfg.numAttrs = 1;
    cudaLaunchKernelEx(&cfg, rv_kernel, x, (const float*)att_out, out);
}

// round 15
// speedup vs baseline: 1.3974x; 1.3974x over previous
#include <cuda_runtime.h>
#include <cstdint>

// Problem constants
#define BATCH      256
#define TREES      64
#define FEAT       16080        // 120*134
#define MASK_W     1000
#define K_TOP      200
#define ROW_F4     (FEAT / 4)   // 4020
#define LIVE_F4    (MASK_W / 4) // 250  (columns [0,1000) hold all nonzeros)
#define NROWS      (BATCH * TREES)   // 16384 rv rows
#define NROWS_ALL  (NROWS + TREES)   // + 64 attention rows = 16448

// ---------------------------------------------------------------------------
// Kernel A: block-per-tree exact top-200 via __syncthreads_count binary search.
//   Triggers programmatic launch completion at entry so the store kernel's
//   grid launches immediately and overlaps this one (64 blocks => all wave-1
//   resident => all triggers fire instantly).
// ---------------------------------------------------------------------------
__global__ __launch_bounds__(1024)
void topk_kernel(const float* __restrict__ mask, float* __restrict__ att_out)
{
    // Let the dependent rv_kernel grid begin launching now; its att-reading
    // blocks still wait for this grid's completion via
    // cudaGridDependencySynchronize().
    cudaTriggerProgrammaticLaunchCompletion();

    const int t   = blockIdx.x;
    const int tid = threadIdx.x;

    __shared__ unsigned int skey[1024];

    // Load + order-preserving float->uint transform
    float v = 0.0f;
    unsigned int key = 0u;
    if (tid < MASK_W) {
        v = mask[t * MASK_W + tid];
        const int s = __float_as_int(v);
        key = (s < 0) ? ~(unsigned int)s : ((unsigned int)s | 0x80000000u);
    }
    skey[tid] = key;   // consumed only on the rare tie path; the search-loop
                       // barriers below order this write before any read

    // Binary search: thr = max T with count(key >= T) >= K_TOP (200th largest).
    // Sentinel key 0 (tid >= 1000) is never counted: midpoints are >= 1 and
    // finite-float keys are > 0.
    unsigned int lo = 0u, hi = 0xFFFFFFFFu;
    while (lo < hi) {
        const unsigned int mid = lo + ((hi - lo) >> 1) + 1u;   // upper mid
        const int total = __syncthreads_count(key >= mid);
        if (total >= K_TOP) lo = mid; else hi = mid - 1u;
    }
    const unsigned int thr = lo;

    // Strictly-greater / equal counts (block-uniform results)
    const int cgt = __syncthreads_count(key > thr);
    const int ceq = __syncthreads_count(key == thr);
    const int need = K_TOP - cgt;            // equals to accept (1 <= need <= ceq)

    bool sel = (key > thr);
    if (key == thr) {
        if (need >= ceq) {
            sel = true;                      // all ties fit (common case)
        } else {                             // boundary tie: lowest indices win
            int r = 0;
            for (int j = 0; j < tid; ++j) r += (skey[j] == thr);
            sel = (r < need);
        }
    }

    if (tid < MASK_W) {
        att_out[(size_t)t * FEAT + tid] = sel ? (1.0f / (1.0f + expf(-v))) : 0.0f;
    }
}

// ---------------------------------------------------------------------------
// Kernel B: full-output store stream, 4 independent float4 stores per thread
//   (round-9 version + PDL dependency sync).
//   grid = (4, 16448), block = 256. base = bx*256+tid in [0,1024); thread
//   stores columns {base, base+1024, base+2048, base+3072} of its row.
//   Row-major grid: consecutive bids cover the 4 stripes of the same row,
//   so concurrent blocks write contiguous 16 KB spans (DRAM-page friendly).
//   Only bx==0 rv-row blocks read attention, so only they execute
//   cudaGridDependencySynchronize(); the other 75% of blocks stream zero
//   stores with no extra instructions — the store wave stays clean.
// ---------------------------------------------------------------------------
__global__ __launch_bounds__(256)
void rv_kernel(const float* __restrict__ x,
               const float* __restrict__ att,
               float*       __restrict__ out)
{
    const int tid  = threadIdx.x;
    const int base = blockIdx.x * 256 + tid;                 // 0 .. 1023
    const int row  = blockIdx.y;

    float4* dst = reinterpret_cast<float4*>(out + (size_t)row * FEAT);
    float4 z; z.x = 0.f; z.y = 0.f; z.z = 0.f; z.w = 0.f;

    if (row >= NROWS) {                    // attention row: zero tail only
        if (base >= LIVE_F4) dst[base] = z;
        dst[base + 1024] = z;
        dst[base + 2048] = z;
        if (base + 3072 < ROW_F4) dst[base + 3072] = z;
        return;
    }

    const int t = row & (TREES - 1);
    const int b = row >> 6;

    float4 r = z;
    if (base < LIVE_F4) {
        // Wait for topk_kernel's attention writes to be visible.
        cudaGridDependencySynchronize();
        const float4 xa = reinterpret_cast<const float4*>(x   + (size_t)b * FEAT)[base];
        const float4 aa = reinterpret_cast<const float4*>(att + (size_t)t * FEAT)[base];
        r.x = xa.x * aa.x;
        r.y = xa.y * aa.y;
        r.z = xa.z * aa.z;
        r.w = xa.w * aa.w;
    }
    dst[base]        = r;
    dst[base + 1024] = z;
    dst[base + 2048] = z;
    if (base + 3072 < ROW_F4) dst[base + 3072] = z;
}

// ---------------------------------------------------------------------------
// Launch: topk, then rv with programmatic stream serialization (PDL) so the
// rv grid launches and its independent blocks run while topk is in flight.
// ---------------------------------------------------------------------------
extern "C" void kernel_launch(void* const* d_in, const int* in_sizes, int n_in,
                              void* d_out, int out_size)
{
    const float* x    = (const float*)d_in[0];   // (256, 120, 134) fp32
    const float* mask = (const float*)d_in[1];   // (64, 1000) fp32

    float* out = (float*)d_out;
    float* att_out = out + (size_t)NROWS * FEAT; // (64, 16080) appended

    // A) block-per-tree exact top-200 -> attention[t, 0:1000)
    topk_kernel<<<TREES, 1024>>>(mask, att_out);

    // B) full-output store stream, launched with PDL overlap
    cudaLaunchConfig_t cfg = {};
    cfg.gridDim  = dim3(4, NROWS_ALL, 1);
    cfg.blockDim = dim3(256, 1, 1);
    cfg.dynamicSmemBytes = 0;
    cudaLaunchAttribute attr[1];
    attr[0].id = cudaLaunchAttributeProgrammaticStreamSerialization;
    attr[0].val.programmaticStreamSerializationAllowed = 1;
    cfg.attrs = attr;
    cfg.numAttrs = 1;
    cudaLaunchKernelEx(&cfg, rv_kernel, x, (const float*)att_out, out);
}

// round 16
// speedup vs baseline: 1.4046x; 1.0051x over previous
#include <cuda_runtime.h>
#include <cstdint>

// Problem constants
#define BATCH      256
#define TREES      64
#define FEAT       16080        // 120*134
#define MASK_W     1000
#define K_TOP      200
#define ROW_F4     (FEAT / 4)   // 4020
#define LIVE_F4    (MASK_W / 4) // 250  (columns [0,1000) hold all nonzeros)
#define NROWS      (BATCH * TREES)   // 16384 rv rows
#define NROWS_ALL  (NROWS + TREES)   // + 64 attention rows = 16448
#define NBLOCKS    (TREES + NROWS_ALL)

// ---------------------------------------------------------------------------
// ONE kernel, no inter-block dependency:
//   bid in [0,64): tree block t = bid.
//     1) exact top-200 via __syncthreads_count binary search (jax tie-break)
//     2) write attention[t, 0:1000) and cache the values in smem
//     3) write ALL live products out[b*64+t, 0:1000) = x[b,:]*att for b=0..255
//        (1 MB of coalesced float4 stores; x slice is L2-resident)
//   bid >= 64: row = bid-64 in [0,16448): zero columns [250,4020) of that row
//     (covers rv-row tails AND attention-row tails uniformly).
//   Writes are disjoint and each block is self-contained -> no sync/flag/PDL.
//   The 64 heavy blocks hold the lowest bids -> wave-1 resident -> hidden
//   inside the 140us zero-store wave.
// ---------------------------------------------------------------------------
__global__ __launch_bounds__(1024, 2)
void fused_kernel(const float* __restrict__ x,
                  const float* __restrict__ mask,
                  float*       __restrict__ out)
{
    const int tid = threadIdx.x;
    const int bid = blockIdx.x;

    if (bid >= TREES) {
        // ---------------- zero path: one full row tail ----------------
        const int row = bid - TREES;                     // 0 .. 16447
        float4* dst = reinterpret_cast<float4*>(out + (size_t)row * FEAT);
        float4 z; z.x = 0.f; z.y = 0.f; z.z = 0.f; z.w = 0.f;
        if (tid >= LIVE_F4) dst[tid] = z;                // [250,1024)
        dst[tid + 1024] = z;                             // [1024,2048)
        dst[tid + 2048] = z;                             // [2048,3072)
        if (tid + 3072 < ROW_F4) dst[tid + 3072] = z;    // [3072,4020)
        return;
    }

    // ---------------- topk + live path: tree t ----------------
    const int t = bid;

    __shared__ unsigned int skey[1024];
    __shared__ float4       sav[LIVE_F4];                // attention values

    // Load + order-preserving float->uint transform
    float v = 0.0f;
    unsigned int key = 0u;
    if (tid < MASK_W) {
        v = mask[t * MASK_W + tid];
        const int s = __float_as_int(v);
        key = (s < 0) ? ~(unsigned int)s : ((unsigned int)s | 0x80000000u);
    }
    skey[tid] = key;   // consumed only on the rare tie path; the search-loop
                       // barriers below order this write before any read

    // Binary search: thr = max T with count(key >= T) >= K_TOP (200th largest).
    // Sentinel key 0 (tid >= 1000) is never counted: midpoints are >= 1 and
    // finite-float keys are > 0.
    unsigned int lo = 0u, hi = 0xFFFFFFFFu;
    while (lo < hi) {
        const unsigned int mid = lo + ((hi - lo) >> 1) + 1u;   // upper mid
        const int total = __syncthreads_count(key >= mid);
        if (total >= K_TOP) lo = mid; else hi = mid - 1u;
    }
    const unsigned int thr = lo;

    // Strictly-greater / equal counts (block-uniform results)
    const int cgt = __syncthreads_count(key > thr);
    const int ceq = __syncthreads_count(key == thr);
    const int need = K_TOP - cgt;            // equals to accept (1 <= need <= ceq)

    bool sel = (key > thr);
    if (key == thr) {
        if (need >= ceq) {
            sel = true;                      // all ties fit (common case)
        } else {                             // boundary tie: lowest indices win
            int r = 0;
            for (int j = 0; j < tid; ++j) r += (skey[j] == thr);
            sel = (r < need);
        }
    }

    // Attention value; write the attention row and cache in smem
    float av = 0.0f;
    if (tid < MASK_W) {
        av = sel ? (1.0f / (1.0f + expf(-v))) : 0.0f;
        reinterpret_cast<float*>(sav)[tid] = av;
        out[(size_t)(NROWS + t) * FEAT + tid] = av;
    }
    __syncthreads();

    // Live products for all 256 batch rows of this tree.
    // Threads 0..999: 4 rows x 250 float4-cols per iteration, 64 iterations.
    if (tid < MASK_W) {
        const int c4   = tid % LIVE_F4;      // 0..249
        const int rsub = tid / LIVE_F4;      // 0..3
        const float4 a4 = sav[c4];
        #pragma unroll 4
        for (int it = 0; it < BATCH / 4; ++it) {
            const int b = it * 4 + rsub;
            const float4 xa = reinterpret_cast<const float4*>(x + (size_t)b * FEAT)[c4];
            float4 r;
            r.x = xa.x * a4.x;
            r.y = xa.y * a4.y;
            r.z = xa.z * a4.z;
            r.w = xa.w * a4.w;
            reinterpret_cast<float4*>(out + (size_t)(b * TREES + t) * FEAT)[c4] = r;
        }
    }
}

// ---------------------------------------------------------------------------
// Launch: one kernel, one graph node.
// ---------------------------------------------------------------------------
extern "C" void kernel_launch(void* const* d_in, const int* in_sizes, int n_in,
                              void* d_out, int out_size)
{
    const float* x    = (const float*)d_in[0];   // (256, 120, 134) fp32
    const float* mask = (const float*)d_in[1];   // (64, 1000) fp32
    float* out = (float*)d_out;

    fused_kernel<<<NBLOCKS, 1024>>>(x, mask, out);
}

// round 17
// speedup vs baseline: 1.4093x; 1.0034x over previous
#include <cuda_runtime.h>
#include <cstdint>

// Problem constants
#define BATCH      256
#define TREES      64
#define FEAT       16080        // 120*134
#define MASK_W     1000
#define K_TOP      200
#define ROW_F4     (FEAT / 4)   // 4020
#define LIVE_F4    (MASK_W / 4) // 250  (columns [0,1000) hold all nonzeros)
#define NROWS      (BATCH * TREES)   // 16384 rv rows
#define NROWS_ALL  (NROWS + TREES)   // + 64 attention rows = 16448
#define NBLOCKS    (TREES + NROWS_ALL)

// ---------------------------------------------------------------------------
// ONE kernel, no inter-block dependency (converged final version):
//   bid in [0,64): tree block t = bid.
//     1) exact top-200 via __syncthreads_count binary search (jax tie-break)
//     2) write attention[t, 0:1000) and cache the values in smem
//     3) write ALL live products out[b*64+t, 0:1000) = x[b,:]*att for b=0..255
//        (1 MB of coalesced float4 stores; x slice is L2-resident)
//   bid >= 64: row = bid-64 in [0,16448): zero columns [250,4020) of that row
//     (covers rv-row tails AND attention-row tails uniformly).
//   Writes are disjoint and each block is self-contained -> no sync/flag/PDL.
//   The 64 heavy blocks hold the lowest bids -> wave-1 resident -> hidden
//   inside the ~140us zero-store wave. Store stream runs at the measured
//   chip write ceiling (~7.1 TB/s, ~90% of 8 TB/s spec).
// ---------------------------------------------------------------------------
__global__ __launch_bounds__(1024, 2)
void fused_kernel(const float* __restrict__ x,
                  const float* __restrict__ mask,
                  float*       __restrict__ out)
{
    const int tid = threadIdx.x;
    const int bid = blockIdx.x;

    if (bid >= TREES) {
        // ---------------- zero path: one full row tail ----------------
        const int row = bid - TREES;                     // 0 .. 16447
        float4* dst = reinterpret_cast<float4*>(out + (size_t)row * FEAT);
        float4 z; z.x = 0.f; z.y = 0.f; z.z = 0.f; z.w = 0.f;
        if (tid >= LIVE_F4) dst[tid] = z;                // [250,1024)
        dst[tid + 1024] = z;                             // [1024,2048)
        dst[tid + 2048] = z;                             // [2048,3072)
        if (tid + 3072 < ROW_F4) dst[tid + 3072] = z;    // [3072,4020)
        return;
    }

    // ---------------- topk + live path: tree t ----------------
    const int t = bid;

    __shared__ unsigned int skey[1024];
    __shared__ float4       sav[LIVE_F4];                // attention values

    // Load + order-preserving float->uint transform
    float v = 0.0f;
    unsigned int key = 0u;
    if (tid < MASK_W) {
        v = mask[t * MASK_W + tid];
        const int s = __float_as_int(v);
        key = (s < 0) ? ~(unsigned int)s : ((unsigned int)s | 0x80000000u);
    }
    skey[tid] = key;   // consumed only on the rare tie path; the search-loop
                       // barriers below order this write before any read

    // Binary search: thr = max T with count(key >= T) >= K_TOP (200th largest).
    // Sentinel key 0 (tid >= 1000) is never counted: midpoints are >= 1 and
    // finite-float keys are > 0.
    unsigned int lo = 0u, hi = 0xFFFFFFFFu;
    while (lo < hi) {
        const unsigned int mid = lo + ((hi - lo) >> 1) + 1u;   // upper mid
        const int total = __syncthreads_count(key >= mid);
        if (total >= K_TOP) lo = mid; else hi = mid - 1u;
    }
    const unsigned int thr = lo;

    // Strictly-greater / equal counts (block-uniform results)
    const int cgt = __syncthreads_count(key > thr);
    const int ceq = __syncthreads_count(key == thr);
    const int need = K_TOP - cgt;            // equals to accept (1 <= need <= ceq)

    bool sel = (key > thr);
    if (key == thr) {
        if (need >= ceq) {
            sel = true;                      // all ties fit (common case)
        } else {                             // boundary tie: lowest indices win
            int r = 0;
            for (int j = 0; j < tid; ++j) r += (skey[j] == thr);
            sel = (r < need);
        }
    }

    // Attention value; write the attention row and cache in smem
    float av = 0.0f;
    if (tid < MASK_W) {
        av = sel ? (1.0f / (1.0f + expf(-v))) : 0.0f;
        reinterpret_cast<float*>(sav)[tid] = av;
        out[(size_t)(NROWS + t) * FEAT + tid] = av;
    }
    __syncthreads();

    // Live products for all 256 batch rows of this tree.
    // Threads 0..999: 4 rows x 250 float4-cols per iteration, 64 iterations.
    if (tid < MASK_W) {
        const int c4   = tid % LIVE_F4;      // 0..249
        const int rsub = tid / LIVE_F4;      // 0..3
        const float4 a4 = sav[c4];
        #pragma unroll 4
        for (int it = 0; it < BATCH / 4; ++it) {
            const int b = it * 4 + rsub;
            const float4 xa = reinterpret_cast<const float4*>(x + (size_t)b * FEAT)[c4];
            float4 r;
            r.x = xa.x * a4.x;
            r.y = xa.y * a4.y;
            r.z = xa.z * a4.z;
            r.w = xa.w * a4.w;
            reinterpret_cast<float4*>(out + (size_t)(b * TREES + t) * FEAT)[c4] = r;
        }
    }
}

// ---------------------------------------------------------------------------
// Launch: one kernel, one graph node.
// ---------------------------------------------------------------------------
extern "C" void kernel_launch(void* const* d_in, const int* in_sizes, int n_in,
                              void* d_out, int out_size)
{
    const float* x    = (const float*)d_in[0];   // (256, 120, 134) fp32
    const float* mask = (const float*)d_in[1];   // (64, 1000) fp32
    float* out = (float*)d_out;

    fused_kernel<<<NBLOCKS, 1024>>>(x, mask, out);
}